// round 2
// baseline (speedup 1.0000x reference)
#include <cuda_runtime.h>

#define BN 2
#define LN 12288
#define KN 32
#define IN 768
#define CT 128
#define CA 16
#define RMS_EPS 1e-6f

// Scratch (allocs are banned; device globals are the sanctioned workaround)
__device__ float g_Sl[BN * LN * CA];                  // 1.5 MB
__device__ float g_Sm[BN * LN * CA];                  // 1.5 MB
__device__ float g_Zp[(size_t)IN * IN * CA];          // 37.75 MB

// ---------------------------------------------------------------------------
// Kernel 1: S_l / S_m projections.  row = b*L + l over C_L [B*L, CT].
// relu(x) @ W_single_l and @ W_single_m, both [CT, CA].
// ---------------------------------------------------------------------------
__global__ void __launch_bounds__(256) sproj_kernel(
    const float* __restrict__ CL,
    const float* __restrict__ Wl,
    const float* __restrict__ Wm)
{
    __shared__ float sWl[CT * CA];
    __shared__ float sWm[CT * CA];
    for (int i = threadIdx.x; i < CT * CA; i += blockDim.x) {
        sWl[i] = Wl[i];
        sWm[i] = Wm[i];
    }
    __syncthreads();

    int row = blockIdx.x * blockDim.x + threadIdx.x;
    if (row >= BN * LN) return;

    const float4* xr = reinterpret_cast<const float4*>(CL + (size_t)row * CT);

    float al[CA], am[CA];
#pragma unroll
    for (int c = 0; c < CA; c++) { al[c] = 0.f; am[c] = 0.f; }

#pragma unroll 2
    for (int i = 0; i < CT / 4; i++) {
        float4 v = __ldg(xr + i);
        float xv[4] = {v.x, v.y, v.z, v.w};
#pragma unroll
        for (int j = 0; j < 4; j++) {
            float x = fmaxf(xv[j], 0.f);
            int t = i * 4 + j;
            const float4* wl4 = reinterpret_cast<const float4*>(sWl + t * CA);
            const float4* wm4 = reinterpret_cast<const float4*>(sWm + t * CA);
#pragma unroll
            for (int cc = 0; cc < 4; cc++) {
                float4 wl = wl4[cc];
                float4 wm = wm4[cc];
                al[cc * 4 + 0] = fmaf(x, wl.x, al[cc * 4 + 0]);
                al[cc * 4 + 1] = fmaf(x, wl.y, al[cc * 4 + 1]);
                al[cc * 4 + 2] = fmaf(x, wl.z, al[cc * 4 + 2]);
                al[cc * 4 + 3] = fmaf(x, wl.w, al[cc * 4 + 3]);
                am[cc * 4 + 0] = fmaf(x, wm.x, am[cc * 4 + 0]);
                am[cc * 4 + 1] = fmaf(x, wm.y, am[cc * 4 + 1]);
                am[cc * 4 + 2] = fmaf(x, wm.z, am[cc * 4 + 2]);
                am[cc * 4 + 3] = fmaf(x, wm.w, am[cc * 4 + 3]);
            }
        }
    }

    float4* ol = reinterpret_cast<float4*>(g_Sl + (size_t)row * CA);
    float4* om = reinterpret_cast<float4*>(g_Sm + (size_t)row * CA);
#pragma unroll
    for (int cc = 0; cc < 4; cc++) {
        ol[cc] = make_float4(al[cc * 4 + 0], al[cc * 4 + 1], al[cc * 4 + 2], al[cc * 4 + 3]);
        om[cc] = make_float4(am[cc * 4 + 0], am[cc * 4 + 1], am[cc * 4 + 2], am[cc * 4 + 3]);
    }
}

// ---------------------------------------------------------------------------
// Kernel 2: Z_proc[r, c] = rmsnorm(Z[r, :]) * rms_w @ W_z.
// RMS scale is linear -> fold rms_w into W, accumulate unnormalized, scale at end.
// Thread-per-row, W (folded) in shared, broadcast reads.
// ---------------------------------------------------------------------------
__global__ void __launch_bounds__(256) zproc_kernel(
    const float* __restrict__ Z,
    const float* __restrict__ rmsw,
    const float* __restrict__ Wz)
{
    __shared__ float sW[CT * CA];
    for (int i = threadIdx.x; i < CT * CA; i += blockDim.x)
        sW[i] = rmsw[i / CA] * Wz[i];
    __syncthreads();

    int row = blockIdx.x * blockDim.x + threadIdx.x;
    if (row >= IN * IN) return;

    const float4* zr = reinterpret_cast<const float4*>(Z + (size_t)row * CT);

    float acc[CA];
#pragma unroll
    for (int c = 0; c < CA; c++) acc[c] = 0.f;
    float ss = 0.f;

#pragma unroll 2
    for (int i = 0; i < CT / 4; i++) {
        float4 v = __ldg(zr + i);
        float xv[4] = {v.x, v.y, v.z, v.w};
#pragma unroll
        for (int j = 0; j < 4; j++) {
            float x = xv[j];
            ss = fmaf(x, x, ss);
            const float4* w4 = reinterpret_cast<const float4*>(sW + (i * 4 + j) * CA);
#pragma unroll
            for (int cc = 0; cc < 4; cc++) {
                float4 w = w4[cc];
                acc[cc * 4 + 0] = fmaf(x, w.x, acc[cc * 4 + 0]);
                acc[cc * 4 + 1] = fmaf(x, w.y, acc[cc * 4 + 1]);
                acc[cc * 4 + 2] = fmaf(x, w.z, acc[cc * 4 + 2]);
                acc[cc * 4 + 3] = fmaf(x, w.w, acc[cc * 4 + 3]);
            }
        }
    }

    float scale = rsqrtf(ss * (1.0f / CT) + RMS_EPS);
    float4* o = reinterpret_cast<float4*>(g_Zp + (size_t)row * CA);
#pragma unroll
    for (int cc = 0; cc < 4; cc++)
        o[cc] = make_float4(acc[cc * 4 + 0] * scale, acc[cc * 4 + 1] * scale,
                            acc[cc * 4 + 2] * scale, acc[cc * 4 + 3] * scale);
}

// ---------------------------------------------------------------------------
// Kernel 3: pair assembly + residual MLP.  warp = one (b,l) query, lane = k.
// ---------------------------------------------------------------------------
__device__ __forceinline__ void mlp_layer(const float* in, const float* W, float* out)
{
#pragma unroll
    for (int c = 0; c < CA; c++) out[c] = 0.f;
#pragma unroll
    for (int j = 0; j < CA; j++) {
        float r = fmaxf(in[j], 0.f);
        const float4* w4 = reinterpret_cast<const float4*>(W + j * CA);
#pragma unroll
        for (int cc = 0; cc < 4; cc++) {
            float4 w = w4[cc];
            out[cc * 4 + 0] = fmaf(r, w.x, out[cc * 4 + 0]);
            out[cc * 4 + 1] = fmaf(r, w.y, out[cc * 4 + 1]);
            out[cc * 4 + 2] = fmaf(r, w.z, out[cc * 4 + 2]);
            out[cc * 4 + 3] = fmaf(r, w.w, out[cc * 4 + 3]);
        }
    }
}

__global__ void __launch_bounds__(128) pair_kernel(
    const float* __restrict__ motif_pos,
    const float* __restrict__ is_motif_coord,   // bool serialized as float32
    const float* __restrict__ ref_pos,
    const int* __restrict__ ref_space_uid,
    const float* __restrict__ is_motif_seq,     // bool serialized as float32
    const int* __restrict__ indices,
    const int* __restrict__ tok_idx,
    const float* __restrict__ Wd_m, const float* __restrict__ Wi_m, const float* __restrict__ Wk_m,
    const float* __restrict__ Wd_r, const float* __restrict__ Wi_r, const float* __restrict__ Wk_r,
    const float* __restrict__ W1, const float* __restrict__ W2, const float* __restrict__ W3,
    float* __restrict__ out)
{
    __shared__ float sWd_m[3 * CA], sWi_m[CA], sWk_m[CA];
    __shared__ float sWd_r[3 * CA], sWi_r[CA], sWk_r[CA];
    __shared__ float sW1[CA * CA], sW2[CA * CA], sW3[CA * CA];

    int t = threadIdx.x;
    for (int i = t; i < 3 * CA; i += 128) { sWd_m[i] = Wd_m[i]; sWd_r[i] = Wd_r[i]; }
    for (int i = t; i < CA; i += 128) {
        sWi_m[i] = Wi_m[i]; sWk_m[i] = Wk_m[i];
        sWi_r[i] = Wi_r[i]; sWk_r[i] = Wk_r[i];
    }
    for (int i = t; i < CA * CA; i += 128) { sW1[i] = W1[i]; sW2[i] = W2[i]; sW3[i] = W3[i]; }
    __syncthreads();

    int q = blockIdx.x * 4 + (t >> 5);   // query index in [0, B*L)
    if (q >= BN * LN) return;
    int lane = t & 31;                   // k
    int b = q / LN;
    int l = q - b * LN;

    int idx = indices[(size_t)q * KN + lane];
    idx = min(max(idx, 0), LN - 1);

    float P[CA];

    // S_l (query, warp-uniform) + S_m gather (key)
    {
        const float4* slp = reinterpret_cast<const float4*>(g_Sl + (size_t)q * CA);
        const float4* smp = reinterpret_cast<const float4*>(g_Sm + ((size_t)b * LN + idx) * CA);
#pragma unroll
        for (int cc = 0; cc < 4; cc++) {
            float4 a = __ldg(slp + cc);
            float4 m = __ldg(smp + cc);
            P[cc * 4 + 0] = a.x + m.x;
            P[cc * 4 + 1] = a.y + m.y;
            P[cc * 4 + 2] = a.z + m.z;
            P[cc * 4 + 3] = a.w + m.w;
        }
    }

    // motif-position branch: query mask AND key mask (0/1 masks, mask^2 == mask)
    if (is_motif_coord[l] != 0.f && is_motif_coord[idx] != 0.f) {
        float dx = motif_pos[l * 3 + 0] - motif_pos[idx * 3 + 0];
        float dy = motif_pos[l * 3 + 1] - motif_pos[idx * 3 + 1];
        float dz = motif_pos[l * 3 + 2] - motif_pos[idx * 3 + 2];
        float inv = 1.0f / (1.0f + dx * dx + dy * dy + dz * dz);
#pragma unroll
        for (int c = 0; c < CA; c++)
            P[c] += dx * sWd_m[c] + dy * sWd_m[CA + c] + dz * sWd_m[2 * CA + c]
                  + inv * sWi_m[c] + sWk_m[c];
    }

    // ref-position branch: query is_motif_seq AND (same uid AND key is_motif_seq)
    if (is_motif_seq[l] != 0.f) {
        if (ref_space_uid[idx] == ref_space_uid[l] && is_motif_seq[idx] != 0.f) {
            float dx = ref_pos[l * 3 + 0] - ref_pos[idx * 3 + 0];
            float dy = ref_pos[l * 3 + 1] - ref_pos[idx * 3 + 1];
            float dz = ref_pos[l * 3 + 2] - ref_pos[idx * 3 + 2];
            float inv = 1.0f / (1.0f + dx * dx + dy * dy + dz * dz);
#pragma unroll
            for (int c = 0; c < CA; c++)
                P[c] += dx * sWd_r[c] + dy * sWd_r[CA + c] + dz * sWd_r[2 * CA + c]
                      + inv * sWi_r[c] + sWk_r[c];
        }
    }

    // token-pair Z gather
    {
        int tq = min(max(tok_idx[l], 0), IN - 1);
        int tk = min(max(tok_idx[idx], 0), IN - 1);
        const float4* zp = reinterpret_cast<const float4*>(g_Zp + ((size_t)tq * IN + tk) * CA);
#pragma unroll
        for (int cc = 0; cc < 4; cc++) {
            float4 z = __ldg(zp + cc);
            P[cc * 4 + 0] += z.x;
            P[cc * 4 + 1] += z.y;
            P[cc * 4 + 2] += z.z;
            P[cc * 4 + 3] += z.w;
        }
    }

    // residual MLP: h = relu->W1 -> relu->W2 -> relu->W3 ; out = P + h
    float h0[CA], h1[CA];
    mlp_layer(P,  sW1, h0);
    mlp_layer(h0, sW2, h1);
    mlp_layer(h1, sW3, h0);

    float4* op = reinterpret_cast<float4*>(out + ((size_t)q * KN + lane) * CA);
#pragma unroll
    for (int cc = 0; cc < 4; cc++)
        op[cc] = make_float4(P[cc * 4 + 0] + h0[cc * 4 + 0],
                             P[cc * 4 + 1] + h0[cc * 4 + 1],
                             P[cc * 4 + 2] + h0[cc * 4 + 2],
                             P[cc * 4 + 3] + h0[cc * 4 + 3]);
}

// ---------------------------------------------------------------------------
extern "C" void kernel_launch(void* const* d_in, const int* in_sizes, int n_in,
                              void* d_out, int out_size)
{
    const float* motif_pos      = (const float*)d_in[0];
    const float* is_motif_coord = (const float*)d_in[1];
    const float* ref_pos        = (const float*)d_in[2];
    const int*   ref_space_uid  = (const int*)d_in[3];
    const float* is_motif_seq   = (const float*)d_in[4];
    const int*   indices        = (const int*)d_in[5];
    const float* C_L            = (const float*)d_in[6];
    const float* Z              = (const float*)d_in[7];
    const int*   tok_idx        = (const int*)d_in[8];
    const float* W_d_m          = (const float*)d_in[9];
    const float* W_inv_m        = (const float*)d_in[10];
    const float* W_mask_m       = (const float*)d_in[11];
    const float* W_d_r          = (const float*)d_in[12];
    const float* W_inv_r        = (const float*)d_in[13];
    const float* W_mask_r       = (const float*)d_in[14];
    const float* W_single_l     = (const float*)d_in[15];
    const float* W_single_m     = (const float*)d_in[16];
    const float* rms_w          = (const float*)d_in[17];
    const float* W_z            = (const float*)d_in[18];
    const float* W_mlp1         = (const float*)d_in[19];
    const float* W_mlp2         = (const float*)d_in[20];
    const float* W_mlp3         = (const float*)d_in[21];
    float* out = (float*)d_out;

    sproj_kernel<<<(BN * LN + 255) / 256, 256>>>(C_L, W_single_l, W_single_m);
    zproc_kernel<<<(IN * IN + 255) / 256, 256>>>(Z, rms_w, W_z);
    pair_kernel<<<(BN * LN + 3) / 4, 128>>>(
        motif_pos, is_motif_coord, ref_pos, ref_space_uid, is_motif_seq,
        indices, tok_idx,
        W_d_m, W_inv_m, W_mask_m, W_d_r, W_inv_r, W_mask_r,
        W_mlp1, W_mlp2, W_mlp3, out);
}